// round 9
// baseline (speedup 1.0000x reference)
#include <cuda_runtime.h>

#define T_LEN 16384
#define NXW   128
#define NH    512
#define STEPS (T_LEN - NXW)       /* 16256 */
#define NROWS (4 * NH)            /* 2048 gate rows */

#define NCTA  128
#define TPB   128                 /* 4 warps -> 512 warps total = NH */
#define WPC   (TPB / 32)

/* ---- static scratch ---- */
__device__ __align__(16) float  g_XG[(size_t)NROWS * STEPS];     /* [row][t], row=h*4+g */
__device__ __align__(16) float2 g_HP[(size_t)(STEPS + 1) * NH];  /* (h_value, tag_bits) */

/* =================== init =================== */
__global__ void init_kernel() {
    int i = blockIdx.x * blockDim.x + threadIdx.x;
    if (i < NH) g_HP[i] = make_float2(0.0f, __uint_as_float(0u));
}

/* =================== gate precompute =================== */
#define GT_TPB  128
#define GT_TT   512
#define GT_ROWS 16

__global__ void __launch_bounds__(GT_TPB) gates_kernel(
    const float* __restrict__ x,
    const float* __restrict__ Wf, const float* __restrict__ Wi,
    const float* __restrict__ Wo, const float* __restrict__ Wc,
    const float* __restrict__ bf, const float* __restrict__ bi,
    const float* __restrict__ bo, const float* __restrict__ bc)
{
    __shared__ float xs[GT_TT + NXW];
    __shared__ float ws[GT_ROWS * NXW];
    __shared__ float bs[GT_ROWS];

    const int tid = threadIdx.x;
    const int t0  = blockIdx.x * GT_TT;
    const int r0  = blockIdx.y * GT_ROWS;

    for (int i = tid; i < GT_TT + NXW; i += GT_TPB) {
        int xi = t0 + i;
        xs[i] = (xi < T_LEN) ? x[xi] : 0.0f;
    }
    for (int i = tid; i < GT_ROWS * NXW; i += GT_TPB) {
        int lr = i >> 7;
        int k  = i & 127;
        int r  = r0 + lr;
        int g  = r & 3;
        int h  = r >> 2;
        const float* W = (g == 0) ? Wf : (g == 1) ? Wi : (g == 2) ? Wo : Wc;
        ws[i] = W[h * NXW + k];
    }
    if (tid < GT_ROWS) {
        int r = r0 + tid;
        int g = r & 3;
        int h = r >> 2;
        const float* B = (g == 0) ? bf : (g == 1) ? bi : (g == 2) ? bo : bc;
        bs[tid] = B[h];
    }
    __syncthreads();

    float acc0[GT_ROWS], acc1[GT_ROWS], acc2[GT_ROWS], acc3[GT_ROWS];
#pragma unroll
    for (int lr = 0; lr < GT_ROWS; lr++) { acc0[lr] = acc1[lr] = acc2[lr] = acc3[lr] = 0.0f; }

#pragma unroll 4
    for (int k = 0; k < NXW; k++) {
        float x0 = xs[tid + k];
        float x1 = xs[tid + 128 + k];
        float x2 = xs[tid + 256 + k];
        float x3 = xs[tid + 384 + k];
#pragma unroll
        for (int lr = 0; lr < GT_ROWS; lr++) {
            float w = ws[lr * NXW + k];
            acc0[lr] = fmaf(w, x0, acc0[lr]);
            acc1[lr] = fmaf(w, x1, acc1[lr]);
            acc2[lr] = fmaf(w, x2, acc2[lr]);
            acc3[lr] = fmaf(w, x3, acc3[lr]);
        }
    }

#pragma unroll
    for (int lr = 0; lr < GT_ROWS; lr++) {
        size_t base = (size_t)(r0 + lr) * STEPS;
        int t;
        t = t0 + tid;       if (t < STEPS) g_XG[base + t] = acc0[lr] + bs[lr];
        t = t0 + 128 + tid; if (t < STEPS) g_XG[base + t] = acc1[lr] + bs[lr];
        t = t0 + 256 + tid; if (t < STEPS) g_XG[base + t] = acc2[lr] + bs[lr];
        t = t0 + 384 + tid; if (t < STEPS) g_XG[base + t] = acc3[lr] + bs[lr];
    }
}

/* =================== recurrence =================== */
__device__ __forceinline__ float tanh_fast(float x) {
    float y;
    asm("tanh.approx.f32 %0, %1;" : "=f"(y) : "f"(x));
    return y;
}
__device__ __forceinline__ float sigmoid_fast(float x) {
    return fmaf(0.5f, tanh_fast(0.5f * x), 0.5f);
}

__device__ __forceinline__ float4 poll_ld(const void* p) {
    float4 v;
    asm volatile("ld.global.cg.v4.f32 {%0,%1,%2,%3}, [%4];"
                 : "=f"(v.x), "=f"(v.y), "=f"(v.z), "=f"(v.w)
                 : "l"(p) : "memory");
    return v;
}

__device__ __forceinline__ unsigned long long pack2(float lo, float hi) {
    unsigned long long r;
    asm("mov.b64 %0, {%1, %2};" : "=l"(r) : "f"(lo), "f"(hi));
    return r;
}
__device__ __forceinline__ void ffma2(unsigned long long& d,
                                      unsigned long long a,
                                      unsigned long long b) {
    asm("fma.rn.f32x2 %0, %1, %2, %0;" : "+l"(d) : "l"(a), "l"(b));
}
__device__ __forceinline__ float unpack_sum(unsigned long long v) {
    float lo, hi;
    asm("mov.b64 {%0, %1}, %2;" : "=f"(lo), "=f"(hi) : "l"(v));
    return lo + hi;
}

__global__ void __launch_bounds__(TPB, 1) rec_kernel(
    const float* __restrict__ Uf, const float* __restrict__ Ui,
    const float* __restrict__ Uo, const float* __restrict__ Uc)
{
    const int tid   = threadIdx.x;
    const int w     = tid >> 5;
    const int lane  = tid & 31;
    const int h_idx = blockIdx.x * WPC + w;      /* one warp per hidden unit */

    /* U weight pairs matched to entry order: lane L, slot j -> entries {j*64+2L, j*64+2L+1} */
    const size_t ub = (size_t)h_idx * NH + 2 * lane;
    unsigned long long wf[8], wi[8], wo[8], wc[8];
#pragma unroll
    for (int j = 0; j < 8; j++) {
        wf[j] = *(const unsigned long long*)(Uf + ub + j * 64);
        wi[j] = *(const unsigned long long*)(Ui + ub + j * 64);
        wo[j] = *(const unsigned long long*)(Uo + ub + j * 64);
        wc[j] = *(const unsigned long long*)(Uc + ub + j * 64);
    }

    /* gate precompute streams, depth-2 prefetch */
    const float* xf = g_XG + (size_t)(h_idx * 4 + 0) * STEPS;
    const float* xi = g_XG + (size_t)(h_idx * 4 + 1) * STEPS;
    const float* xo = g_XG + (size_t)(h_idx * 4 + 2) * STEPS;
    const float* xc = g_XG + (size_t)(h_idx * 4 + 3) * STEPS;

    float pf0 = __ldcg(xf + 0), pi0 = __ldcg(xi + 0), po0 = __ldcg(xo + 0), pc0 = __ldcg(xc + 0);
    float pf1 = __ldcg(xf + 1), pi1 = __ldcg(xi + 1), po1 = __ldcg(xo + 1), pc1 = __ldcg(xc + 1);

    float c = 0.0f;   /* cell state, replicated across lanes */

#pragma unroll 2
    for (int t = 0; t < STEPS; t++) {
        const int p = t & 1;
        float xgf = p ? pf1 : pf0;
        float xgi = p ? pi1 : pi0;
        float xgo = p ? po1 : po0;
        float xgc = p ? pc1 : pc0;
        if (t + 2 < STEPS) {
            if (p) { pf1 = __ldcg(xf + t + 2); pi1 = __ldcg(xi + t + 2);
                     po1 = __ldcg(xo + t + 2); pc1 = __ldcg(xc + t + 2); }
            else   { pf0 = __ldcg(xf + t + 2); pi0 = __ldcg(xi + t + 2);
                     po0 = __ldcg(xo + t + 2); pc0 = __ldcg(xc + t + 2); }
        }

        /* ---- poll h(t): sticky per-slot freshness, re-poll only stale slots ---- */
        const char* rowp = (const char*)(g_HP + (size_t)t * NH) + lane * 16;
        const unsigned tgt = (unsigned)t;
        float4 v0, v1, v2, v3, v4, v5, v6, v7;
        unsigned fresh = 0u;

#define POLL_SLOT(J, V)                                                        \
        if (!(fresh & (1u << J))) {                                            \
            V = poll_ld(rowp + J * 512);                                       \
            bool ok = (__float_as_uint(V.y) == tgt)                            \
                    & (__float_as_uint(V.w) == tgt);                           \
            if (__all_sync(0xffffffffu, ok)) fresh |= (1u << J);               \
        }
        for (;;) {
            POLL_SLOT(0, v0) POLL_SLOT(1, v1) POLL_SLOT(2, v2) POLL_SLOT(3, v3)
            POLL_SLOT(4, v4) POLL_SLOT(5, v5) POLL_SLOT(6, v6) POLL_SLOT(7, v7)
            if (fresh == 0xFFu) break;
            __nanosleep(20);
        }
#undef POLL_SLOT

        /* ---- 4 dots via packed f32x2 FMA ---- */
        unsigned long long h0 = pack2(v0.x, v0.z);
        unsigned long long h1 = pack2(v1.x, v1.z);
        unsigned long long h2 = pack2(v2.x, v2.z);
        unsigned long long h3 = pack2(v3.x, v3.z);
        unsigned long long h4 = pack2(v4.x, v4.z);
        unsigned long long h5 = pack2(v5.x, v5.z);
        unsigned long long h6 = pack2(v6.x, v6.z);
        unsigned long long h7 = pack2(v7.x, v7.z);

        unsigned long long af2 = 0ull, ai2 = 0ull, ao2 = 0ull, ac2 = 0ull;
#define ACC(J, H)                                                              \
        ffma2(af2, wf[J], H); ffma2(ai2, wi[J], H);                            \
        ffma2(ao2, wo[J], H); ffma2(ac2, wc[J], H);
        ACC(0, h0) ACC(1, h1) ACC(2, h2) ACC(3, h3)
        ACC(4, h4) ACC(5, h5) ACC(6, h6) ACC(7, h7)
#undef ACC

        float af = unpack_sum(af2);
        float ai = unpack_sum(ai2);
        float ao = unpack_sum(ao2);
        float ac = unpack_sum(ac2);

#pragma unroll
        for (int off = 16; off > 0; off >>= 1) {
            af += __shfl_xor_sync(0xffffffffu, af, off);
            ai += __shfl_xor_sync(0xffffffffu, ai, off);
            ao += __shfl_xor_sync(0xffffffffu, ao, off);
            ac += __shfl_xor_sync(0xffffffffu, ac, off);
        }

        float fg = sigmoid_fast(af + xgf);
        float ig = sigmoid_fast(ai + xgi);
        float og = sigmoid_fast(ao + xgo);
        float gg = tanh_fast(ac + xgc);
        c = fmaf(fg, c, ig * gg);
        float hval = og * tanh_fast(c);

        if (lane == 0) {
            float2 pr = make_float2(hval, __uint_as_float((unsigned)(t + 1)));
            __stcg(&g_HP[(size_t)(t + 1) * NH + h_idx], pr);
        }
    }
}

/* =================== output GEMV =================== */
__global__ void __launch_bounds__(256) out_kernel(
    const float* __restrict__ Ahy, const float* __restrict__ by,
    float* __restrict__ out)
{
    const int w    = threadIdx.x >> 5;
    const int lane = threadIdx.x & 31;
    const int t    = blockIdx.x * 8 + w;
    if (t >= STEPS) return;

    const char* rowp = (const char*)(g_HP + (size_t)(t + 1) * NH) + lane * 16;
    const size_t ab  = 2 * lane;
    float a = 0.0f;
#pragma unroll
    for (int j = 0; j < 8; j++) {
        float4 v = *(const float4*)(rowp + j * 512);
        float2 av = *(const float2*)(Ahy + ab + j * 64);
        a = fmaf(av.x, v.x, a);
        a = fmaf(av.y, v.z, a);
    }
    a += __shfl_xor_sync(0xffffffffu, a, 16);
    a += __shfl_xor_sync(0xffffffffu, a, 8);
    a += __shfl_xor_sync(0xffffffffu, a, 4);
    a += __shfl_xor_sync(0xffffffffu, a, 2);
    a += __shfl_xor_sync(0xffffffffu, a, 1);
    if (lane == 0) out[t] = a + by[0];
}

/* =================== launch =================== */
extern "C" void kernel_launch(void* const* d_in, const int* in_sizes, int n_in,
                              void* d_out, int out_size)
{
    const float* x   = (const float*)d_in[0];
    const float* Wf  = (const float*)d_in[1];
    const float* Uf  = (const float*)d_in[2];
    const float* bf  = (const float*)d_in[3];
    const float* Wi  = (const float*)d_in[4];
    const float* Ui  = (const float*)d_in[5];
    const float* bi  = (const float*)d_in[6];
    const float* Wo  = (const float*)d_in[7];
    const float* Uo  = (const float*)d_in[8];
    const float* bo  = (const float*)d_in[9];
    const float* Wc  = (const float*)d_in[10];
    const float* Uc  = (const float*)d_in[11];
    const float* bc  = (const float*)d_in[12];
    const float* Ahy = (const float*)d_in[13];
    const float* by  = (const float*)d_in[14];
    float* out = (float*)d_out;

    init_kernel<<<1, 512>>>();

    dim3 ggrid((STEPS + GT_TT - 1) / GT_TT, NROWS / GT_ROWS);
    gates_kernel<<<ggrid, GT_TPB>>>(x, Wf, Wi, Wo, Wc, bf, bi, bo, bc);

    rec_kernel<<<NCTA, TPB>>>(Uf, Ui, Uo, Uc);

    out_kernel<<<(STEPS + 7) / 8, 256>>>(Ahy, by, out);
}

// round 14
// speedup vs baseline: 3.7995x; 3.7995x over previous
#include <cuda_runtime.h>

#define T_LEN 16384
#define NXW   128
#define NH    512
#define STEPS (T_LEN - NXW)       /* 16256 */
#define NROWS (4 * NH)            /* 2048 gate rows */

#define NCTA  128
#define TPB   128                 /* 4 warps -> 512 warps total = NH */
#define WPC   (TPB / 32)

/* ---- static scratch ---- */
__device__ __align__(16) float  g_XG[(size_t)NROWS * STEPS];     /* [row][t], row=h*4+g */
__device__ __align__(16) float2 g_HP[(size_t)(STEPS + 1) * NH];  /* (h_value, tag_bits) */

/* =================== init =================== */
__global__ void init_kernel() {
    int i = blockIdx.x * blockDim.x + threadIdx.x;
    if (i < NH) g_HP[i] = make_float2(0.0f, __uint_as_float(0u));
}

/* =================== gate precompute =================== */
#define GT_TPB  128
#define GT_TT   512
#define GT_ROWS 16

__global__ void __launch_bounds__(GT_TPB) gates_kernel(
    const float* __restrict__ x,
    const float* __restrict__ Wf, const float* __restrict__ Wi,
    const float* __restrict__ Wo, const float* __restrict__ Wc,
    const float* __restrict__ bf, const float* __restrict__ bi,
    const float* __restrict__ bo, const float* __restrict__ bc)
{
    __shared__ float xs[GT_TT + NXW];
    __shared__ float ws[GT_ROWS * NXW];
    __shared__ float bs[GT_ROWS];

    const int tid = threadIdx.x;
    const int t0  = blockIdx.x * GT_TT;
    const int r0  = blockIdx.y * GT_ROWS;

    for (int i = tid; i < GT_TT + NXW; i += GT_TPB) {
        int xi = t0 + i;
        xs[i] = (xi < T_LEN) ? x[xi] : 0.0f;
    }
    for (int i = tid; i < GT_ROWS * NXW; i += GT_TPB) {
        int lr = i >> 7;
        int k  = i & 127;
        int r  = r0 + lr;
        int g  = r & 3;
        int h  = r >> 2;
        const float* W = (g == 0) ? Wf : (g == 1) ? Wi : (g == 2) ? Wo : Wc;
        ws[i] = W[h * NXW + k];
    }
    if (tid < GT_ROWS) {
        int r = r0 + tid;
        int g = r & 3;
        int h = r >> 2;
        const float* B = (g == 0) ? bf : (g == 1) ? bi : (g == 2) ? bo : bc;
        bs[tid] = B[h];
    }
    __syncthreads();

    float acc0[GT_ROWS], acc1[GT_ROWS], acc2[GT_ROWS], acc3[GT_ROWS];
#pragma unroll
    for (int lr = 0; lr < GT_ROWS; lr++) { acc0[lr] = acc1[lr] = acc2[lr] = acc3[lr] = 0.0f; }

#pragma unroll 4
    for (int k = 0; k < NXW; k++) {
        float x0 = xs[tid + k];
        float x1 = xs[tid + 128 + k];
        float x2 = xs[tid + 256 + k];
        float x3 = xs[tid + 384 + k];
#pragma unroll
        for (int lr = 0; lr < GT_ROWS; lr++) {
            float w = ws[lr * NXW + k];
            acc0[lr] = fmaf(w, x0, acc0[lr]);
            acc1[lr] = fmaf(w, x1, acc1[lr]);
            acc2[lr] = fmaf(w, x2, acc2[lr]);
            acc3[lr] = fmaf(w, x3, acc3[lr]);
        }
    }

#pragma unroll
    for (int lr = 0; lr < GT_ROWS; lr++) {
        size_t base = (size_t)(r0 + lr) * STEPS;
        int t;
        t = t0 + tid;       if (t < STEPS) g_XG[base + t] = acc0[lr] + bs[lr];
        t = t0 + 128 + tid; if (t < STEPS) g_XG[base + t] = acc1[lr] + bs[lr];
        t = t0 + 256 + tid; if (t < STEPS) g_XG[base + t] = acc2[lr] + bs[lr];
        t = t0 + 384 + tid; if (t < STEPS) g_XG[base + t] = acc3[lr] + bs[lr];
    }
}

/* =================== recurrence =================== */
__device__ __forceinline__ float tanh_fast(float x) {
    float y;
    asm("tanh.approx.f32 %0, %1;" : "=f"(y) : "f"(x));
    return y;
}
__device__ __forceinline__ float sigmoid_fast(float x) {
    return fmaf(0.5f, tanh_fast(0.5f * x), 0.5f);
}

__device__ __forceinline__ float4 poll_ld(const void* p) {
    float4 v;
    asm volatile("ld.global.cg.v4.f32 {%0,%1,%2,%3}, [%4];"
                 : "=f"(v.x), "=f"(v.y), "=f"(v.z), "=f"(v.w)
                 : "l"(p) : "memory");
    return v;
}

__device__ __forceinline__ unsigned long long pack2(float lo, float hi) {
    unsigned long long r;
    asm("mov.b64 %0, {%1, %2};" : "=l"(r) : "f"(lo), "f"(hi));
    return r;
}
__device__ __forceinline__ void ffma2(unsigned long long& d,
                                      unsigned long long a,
                                      unsigned long long b) {
    asm("fma.rn.f32x2 %0, %1, %2, %0;" : "+l"(d) : "l"(a), "l"(b));
}
__device__ __forceinline__ float unpack_sum(unsigned long long v) {
    float lo, hi;
    asm("mov.b64 {%0, %1}, %2;" : "=f"(lo), "=f"(hi) : "l"(v));
    return lo + hi;
}

__global__ void __launch_bounds__(TPB, 1) rec_kernel(
    const float* __restrict__ Uf, const float* __restrict__ Ui,
    const float* __restrict__ Uo, const float* __restrict__ Uc)
{
    const int tid   = threadIdx.x;
    const int w     = tid >> 5;
    const int lane  = tid & 31;
    const int h_idx = blockIdx.x * WPC + w;      /* one warp per hidden unit */

    /* U weight pairs matched to the coalesced entry order:
       lane L, slot j covers h entries {j*64+2L, j*64+2L+1} */
    const size_t ub = (size_t)h_idx * NH + 2 * lane;
    unsigned long long wf[8], wi[8], wo[8], wc[8];
#pragma unroll
    for (int j = 0; j < 8; j++) {
        wf[j] = *(const unsigned long long*)(Uf + ub + j * 64);
        wi[j] = *(const unsigned long long*)(Ui + ub + j * 64);
        wo[j] = *(const unsigned long long*)(Uo + ub + j * 64);
        wc[j] = *(const unsigned long long*)(Uc + ub + j * 64);
    }

    /* gate precompute streams, depth-2 prefetch */
    const float* xf = g_XG + (size_t)(h_idx * 4 + 0) * STEPS;
    const float* xi = g_XG + (size_t)(h_idx * 4 + 1) * STEPS;
    const float* xo = g_XG + (size_t)(h_idx * 4 + 2) * STEPS;
    const float* xc = g_XG + (size_t)(h_idx * 4 + 3) * STEPS;

    float pf0 = __ldcg(xf + 0), pi0 = __ldcg(xi + 0), po0 = __ldcg(xo + 0), pc0 = __ldcg(xc + 0);
    float pf1 = __ldcg(xf + 1), pi1 = __ldcg(xi + 1), po1 = __ldcg(xo + 1), pc1 = __ldcg(xc + 1);

    float c = 0.0f;   /* cell state, replicated across lanes */

#pragma unroll 2
    for (int t = 0; t < STEPS; t++) {
        const int p = t & 1;
        float xgf = p ? pf1 : pf0;
        float xgi = p ? pi1 : pi0;
        float xgo = p ? po1 : po0;
        float xgc = p ? pc1 : pc0;
        if (t + 2 < STEPS) {
            if (p) { pf1 = __ldcg(xf + t + 2); pi1 = __ldcg(xi + t + 2);
                     po1 = __ldcg(xo + t + 2); pc1 = __ldcg(xc + t + 2); }
            else   { pf0 = __ldcg(xf + t + 2); pi0 = __ldcg(xi + t + 2);
                     po0 = __ldcg(xo + t + 2); pc0 = __ldcg(xc + t + 2); }
        }

        /* ---- poll h(t): batched straight-line loads, MLP=8 (R5 pattern) ---- */
        const char* rowp = (const char*)(g_HP + (size_t)t * NH) + lane * 16;
        const unsigned tgt = (unsigned)t;
        float4 v0, v1, v2, v3, v4, v5, v6, v7;
        for (;;) {
            v0 = poll_ld(rowp + 0 * 512); v1 = poll_ld(rowp + 1 * 512);
            v2 = poll_ld(rowp + 2 * 512); v3 = poll_ld(rowp + 3 * 512);
            v4 = poll_ld(rowp + 4 * 512); v5 = poll_ld(rowp + 5 * 512);
            v6 = poll_ld(rowp + 6 * 512); v7 = poll_ld(rowp + 7 * 512);
            bool ok = (__float_as_uint(v0.y) == tgt) & (__float_as_uint(v0.w) == tgt)
                    & (__float_as_uint(v1.y) == tgt) & (__float_as_uint(v1.w) == tgt)
                    & (__float_as_uint(v2.y) == tgt) & (__float_as_uint(v2.w) == tgt)
                    & (__float_as_uint(v3.y) == tgt) & (__float_as_uint(v3.w) == tgt)
                    & (__float_as_uint(v4.y) == tgt) & (__float_as_uint(v4.w) == tgt)
                    & (__float_as_uint(v5.y) == tgt) & (__float_as_uint(v5.w) == tgt)
                    & (__float_as_uint(v6.y) == tgt) & (__float_as_uint(v6.w) == tgt)
                    & (__float_as_uint(v7.y) == tgt) & (__float_as_uint(v7.w) == tgt);
            if (__all_sync(0xffffffffu, ok)) break;
            __nanosleep(30);
        }

        /* ---- 4 dots via packed f32x2 FMA ---- */
        unsigned long long h0 = pack2(v0.x, v0.z);
        unsigned long long h1 = pack2(v1.x, v1.z);
        unsigned long long h2 = pack2(v2.x, v2.z);
        unsigned long long h3 = pack2(v3.x, v3.z);
        unsigned long long h4 = pack2(v4.x, v4.z);
        unsigned long long h5 = pack2(v5.x, v5.z);
        unsigned long long h6 = pack2(v6.x, v6.z);
        unsigned long long h7 = pack2(v7.x, v7.z);

        unsigned long long af2 = 0ull, ai2 = 0ull, ao2 = 0ull, ac2 = 0ull;
#define ACC(J, H)                                                              \
        ffma2(af2, wf[J], H); ffma2(ai2, wi[J], H);                            \
        ffma2(ao2, wo[J], H); ffma2(ac2, wc[J], H);
        ACC(0, h0) ACC(1, h1) ACC(2, h2) ACC(3, h3)
        ACC(4, h4) ACC(5, h5) ACC(6, h6) ACC(7, h7)
#undef ACC

        float af = unpack_sum(af2);
        float ai = unpack_sum(ai2);
        float ao = unpack_sum(ao2);
        float ac = unpack_sum(ac2);

#pragma unroll
        for (int off = 16; off > 0; off >>= 1) {
            af += __shfl_xor_sync(0xffffffffu, af, off);
            ai += __shfl_xor_sync(0xffffffffu, ai, off);
            ao += __shfl_xor_sync(0xffffffffu, ao, off);
            ac += __shfl_xor_sync(0xffffffffu, ac, off);
        }

        float fg = sigmoid_fast(af + xgf);
        float ig = sigmoid_fast(ai + xgi);
        float og = sigmoid_fast(ao + xgo);
        float gg = tanh_fast(ac + xgc);
        c = fmaf(fg, c, ig * gg);
        float hval = og * tanh_fast(c);

        if (lane == 0) {
            float2 pr = make_float2(hval, __uint_as_float((unsigned)(t + 1)));
            __stcg(&g_HP[(size_t)(t + 1) * NH + h_idx], pr);
        }
    }
}

/* =================== output GEMV =================== */
__global__ void __launch_bounds__(256) out_kernel(
    const float* __restrict__ Ahy, const float* __restrict__ by,
    float* __restrict__ out)
{
    const int w    = threadIdx.x >> 5;
    const int lane = threadIdx.x & 31;
    const int t    = blockIdx.x * 8 + w;
    if (t >= STEPS) return;

    const char* rowp = (const char*)(g_HP + (size_t)(t + 1) * NH) + lane * 16;
    const size_t ab  = 2 * lane;
    float a = 0.0f;
#pragma unroll
    for (int j = 0; j < 8; j++) {
        float4 v = *(const float4*)(rowp + j * 512);
        float2 av = *(const float2*)(Ahy + ab + j * 64);
        a = fmaf(av.x, v.x, a);
        a = fmaf(av.y, v.z, a);
    }
    a += __shfl_xor_sync(0xffffffffu, a, 16);
    a += __shfl_xor_sync(0xffffffffu, a, 8);
    a += __shfl_xor_sync(0xffffffffu, a, 4);
    a += __shfl_xor_sync(0xffffffffu, a, 2);
    a += __shfl_xor_sync(0xffffffffu, a, 1);
    if (lane == 0) out[t] = a + by[0];
}

/* =================== launch =================== */
extern "C" void kernel_launch(void* const* d_in, const int* in_sizes, int n_in,
                              void* d_out, int out_size)
{
    const float* x   = (const float*)d_in[0];
    const float* Wf  = (const float*)d_in[1];
    const float* Uf  = (const float*)d_in[2];
    const float* bf  = (const float*)d_in[3];
    const float* Wi  = (const float*)d_in[4];
    const float* Ui  = (const float*)d_in[5];
    const float* bi  = (const float*)d_in[6];
    const float* Wo  = (const float*)d_in[7];
    const float* Uo  = (const float*)d_in[8];
    const float* bo  = (const float*)d_in[9];
    const float* Wc  = (const float*)d_in[10];
    const float* Uc  = (const float*)d_in[11];
    const float* bc  = (const float*)d_in[12];
    const float* Ahy = (const float*)d_in[13];
    const float* by  = (const float*)d_in[14];
    float* out = (float*)d_out;

    init_kernel<<<1, 512>>>();

    dim3 ggrid((STEPS + GT_TT - 1) / GT_TT, NROWS / GT_ROWS);
    gates_kernel<<<ggrid, GT_TPB>>>(x, Wf, Wi, Wo, Wc, bf, bi, bo, bc);

    rec_kernel<<<NCTA, TPB>>>(Uf, Ui, Uo, Uc);

    out_kernel<<<(STEPS + 7) / 8, 256>>>(Ahy, by, out);
}

// round 15
// speedup vs baseline: 5.8680x; 1.5444x over previous
#include <cuda_runtime.h>

#define T_LEN 16384
#define NXW   128
#define NH    512
#define STEPS (T_LEN - NXW)       /* 16256 */
#define NROWS (4 * NH)            /* 2048 gate rows */

#define NCTA  64
#define TPB   256                 /* 8 warps -> 512 warps total = NH */
#define WPC   (TPB / 32)

/* ---- static scratch ---- */
__device__ __align__(16) float g_XG[(size_t)NROWS * STEPS];    /* [row][t], row=h*4+g */
__device__ __align__(16) float g_HV[(size_t)(STEPS + 1) * NH]; /* s = -canon(h); bits!=0 == ready */

/* =================== init =================== */
__global__ void init_kernel() {
    int i = blockIdx.x * blockDim.x + threadIdx.x;
    if (i < NH) g_HV[i] = __uint_as_float(0x80000000u);   /* s = -0.0  (h=0, ready) */
}

/* =================== gate precompute =================== */
#define GT_TPB  128
#define GT_TT   512
#define GT_ROWS 16

__global__ void __launch_bounds__(GT_TPB) gates_kernel(
    const float* __restrict__ x,
    const float* __restrict__ Wf, const float* __restrict__ Wi,
    const float* __restrict__ Wo, const float* __restrict__ Wc,
    const float* __restrict__ bf, const float* __restrict__ bi,
    const float* __restrict__ bo, const float* __restrict__ bc)
{
    __shared__ float xs[GT_TT + NXW];
    __shared__ float ws[GT_ROWS * NXW];
    __shared__ float bs[GT_ROWS];

    const int tid = threadIdx.x;
    const int t0  = blockIdx.x * GT_TT;
    const int r0  = blockIdx.y * GT_ROWS;

    for (int i = tid; i < GT_TT + NXW; i += GT_TPB) {
        int xi = t0 + i;
        xs[i] = (xi < T_LEN) ? x[xi] : 0.0f;
    }
    for (int i = tid; i < GT_ROWS * NXW; i += GT_TPB) {
        int lr = i >> 7;
        int k  = i & 127;
        int r  = r0 + lr;
        int g  = r & 3;
        int h  = r >> 2;
        const float* W = (g == 0) ? Wf : (g == 1) ? Wi : (g == 2) ? Wo : Wc;
        ws[i] = W[h * NXW + k];
    }
    if (tid < GT_ROWS) {
        int r = r0 + tid;
        int g = r & 3;
        int h = r >> 2;
        const float* B = (g == 0) ? bf : (g == 1) ? bi : (g == 2) ? bo : bc;
        bs[tid] = B[h];
    }
    __syncthreads();

    float acc0[GT_ROWS], acc1[GT_ROWS], acc2[GT_ROWS], acc3[GT_ROWS];
#pragma unroll
    for (int lr = 0; lr < GT_ROWS; lr++) { acc0[lr] = acc1[lr] = acc2[lr] = acc3[lr] = 0.0f; }

#pragma unroll 4
    for (int k = 0; k < NXW; k++) {
        float x0 = xs[tid + k];
        float x1 = xs[tid + 128 + k];
        float x2 = xs[tid + 256 + k];
        float x3 = xs[tid + 384 + k];
#pragma unroll
        for (int lr = 0; lr < GT_ROWS; lr++) {
            float w = ws[lr * NXW + k];
            acc0[lr] = fmaf(w, x0, acc0[lr]);
            acc1[lr] = fmaf(w, x1, acc1[lr]);
            acc2[lr] = fmaf(w, x2, acc2[lr]);
            acc3[lr] = fmaf(w, x3, acc3[lr]);
        }
    }

    /* evict-first stores: this 133MB stream must not evict the h-history from L2 */
#pragma unroll
    for (int lr = 0; lr < GT_ROWS; lr++) {
        size_t base = (size_t)(r0 + lr) * STEPS;
        int t;
        t = t0 + tid;       if (t < STEPS) __stcs(&g_XG[base + t], acc0[lr] + bs[lr]);
        t = t0 + 128 + tid; if (t < STEPS) __stcs(&g_XG[base + t], acc1[lr] + bs[lr]);
        t = t0 + 256 + tid; if (t < STEPS) __stcs(&g_XG[base + t], acc2[lr] + bs[lr]);
        t = t0 + 384 + tid; if (t < STEPS) __stcs(&g_XG[base + t], acc3[lr] + bs[lr]);
    }
}

/* =================== recurrence =================== */
__device__ __forceinline__ float tanh_fast(float x) {
    float y;
    asm("tanh.approx.f32 %0, %1;" : "=f"(y) : "f"(x));
    return y;
}
__device__ __forceinline__ float sigmoid_fast(float x) {
    return fmaf(0.5f, tanh_fast(0.5f * x), 0.5f);
}

__device__ __forceinline__ float4 poll_ld(const void* p) {
    float4 v;
    asm volatile("ld.global.cg.v4.f32 {%0,%1,%2,%3}, [%4];"
                 : "=f"(v.x), "=f"(v.y), "=f"(v.z), "=f"(v.w)
                 : "l"(p) : "memory");
    return v;
}

__device__ __forceinline__ unsigned long long pack2(float lo, float hi) {
    unsigned long long r;
    asm("mov.b64 %0, {%1, %2};" : "=l"(r) : "f"(lo), "f"(hi));
    return r;
}
__device__ __forceinline__ void ffma2(unsigned long long& d,
                                      unsigned long long a,
                                      unsigned long long b) {
    asm("fma.rn.f32x2 %0, %1, %2, %0;" : "+l"(d) : "l"(a), "l"(b));
}
__device__ __forceinline__ float unpack_sum(unsigned long long v) {
    float lo, hi;
    asm("mov.b64 {%0, %1}, %2;" : "=f"(lo), "=f"(hi) : "l"(v));
    return lo + hi;
}

__global__ void __launch_bounds__(TPB, 1) rec_kernel(
    const float* __restrict__ Uf, const float* __restrict__ Ui,
    const float* __restrict__ Uo, const float* __restrict__ Uc)
{
    const int tid   = threadIdx.x;
    const int w     = tid >> 5;
    const int lane  = tid & 31;
    const int h_idx = blockIdx.x * WPC + w;      /* one warp per hidden unit */

    /* NEGATED U weight pairs in poll entry order:
       lane L, chunk j (0..3) covers entries j*128 + 4L .. +3 */
    unsigned long long wf[8], wi[8], wo[8], wc[8];
    {
        const size_t uo = (size_t)h_idx * NH + 4 * lane;
#pragma unroll
        for (int j = 0; j < 4; j++) {
            float4 a;
            a = *(const float4*)(Uf + uo + j * 128);
            wf[2*j] = pack2(-a.x, -a.y);  wf[2*j+1] = pack2(-a.z, -a.w);
            a = *(const float4*)(Ui + uo + j * 128);
            wi[2*j] = pack2(-a.x, -a.y);  wi[2*j+1] = pack2(-a.z, -a.w);
            a = *(const float4*)(Uo + uo + j * 128);
            wo[2*j] = pack2(-a.x, -a.y);  wo[2*j+1] = pack2(-a.z, -a.w);
            a = *(const float4*)(Uc + uo + j * 128);
            wc[2*j] = pack2(-a.x, -a.y);  wc[2*j+1] = pack2(-a.z, -a.w);
        }
    }

    /* gate precompute streams, evict-first loads, depth-2 prefetch */
    const float* xf = g_XG + (size_t)(h_idx * 4 + 0) * STEPS;
    const float* xi = g_XG + (size_t)(h_idx * 4 + 1) * STEPS;
    const float* xo = g_XG + (size_t)(h_idx * 4 + 2) * STEPS;
    const float* xc = g_XG + (size_t)(h_idx * 4 + 3) * STEPS;

    float pf0 = __ldcs(xf + 0), pi0 = __ldcs(xi + 0), po0 = __ldcs(xo + 0), pc0 = __ldcs(xc + 0);
    float pf1 = __ldcs(xf + 1), pi1 = __ldcs(xi + 1), po1 = __ldcs(xo + 1), pc1 = __ldcs(xc + 1);

    float c = 0.0f;   /* cell state, replicated across lanes */

#pragma unroll 2
    for (int t = 0; t < STEPS; t++) {
        const int p = t & 1;
        float xgf = p ? pf1 : pf0;
        float xgi = p ? pi1 : pi0;
        float xgo = p ? po1 : po0;
        float xgc = p ? pc1 : pc0;
        if (t + 2 < STEPS) {
            if (p) { pf1 = __ldcs(xf + t + 2); pi1 = __ldcs(xi + t + 2);
                     po1 = __ldcs(xo + t + 2); pc1 = __ldcs(xc + t + 2); }
            else   { pf0 = __ldcs(xf + t + 2); pi0 = __ldcs(xi + t + 2);
                     po0 = __ldcs(xo + t + 2); pc0 = __ldcs(xc + t + 2); }
        }

        /* ---- poll row t: 4 batched coalesced LDG.128, readiness = bits!=0 ---- */
        const char* rowp = (const char*)(g_HV + (size_t)t * NH) + lane * 16;
        float4 v0, v1, v2, v3;
        for (;;) {
            v0 = poll_ld(rowp + 0 * 512); v1 = poll_ld(rowp + 1 * 512);
            v2 = poll_ld(rowp + 2 * 512); v3 = poll_ld(rowp + 3 * 512);
            bool ok = (__float_as_uint(v0.x) != 0u) & (__float_as_uint(v0.y) != 0u)
                    & (__float_as_uint(v0.z) != 0u) & (__float_as_uint(v0.w) != 0u)
                    & (__float_as_uint(v1.x) != 0u) & (__float_as_uint(v1.y) != 0u)
                    & (__float_as_uint(v1.z) != 0u) & (__float_as_uint(v1.w) != 0u)
                    & (__float_as_uint(v2.x) != 0u) & (__float_as_uint(v2.y) != 0u)
                    & (__float_as_uint(v2.z) != 0u) & (__float_as_uint(v2.w) != 0u)
                    & (__float_as_uint(v3.x) != 0u) & (__float_as_uint(v3.y) != 0u)
                    & (__float_as_uint(v3.z) != 0u) & (__float_as_uint(v3.w) != 0u);
            if (__all_sync(0xffffffffu, ok)) break;
            __nanosleep(30);
        }

        /* ---- 4 dots via packed f32x2 FMA: (-w)*(-h) = w*h exactly ---- */
        unsigned long long h0 = pack2(v0.x, v0.y), h1 = pack2(v0.z, v0.w);
        unsigned long long h2 = pack2(v1.x, v1.y), h3 = pack2(v1.z, v1.w);
        unsigned long long h4 = pack2(v2.x, v2.y), h5 = pack2(v2.z, v2.w);
        unsigned long long h6 = pack2(v3.x, v3.y), h7 = pack2(v3.z, v3.w);

        unsigned long long af2 = 0ull, ai2 = 0ull, ao2 = 0ull, ac2 = 0ull;
#define ACC(J, H)                                                              \
        ffma2(af2, wf[J], H); ffma2(ai2, wi[J], H);                            \
        ffma2(ao2, wo[J], H); ffma2(ac2, wc[J], H);
        ACC(0, h0) ACC(1, h1) ACC(2, h2) ACC(3, h3)
        ACC(4, h4) ACC(5, h5) ACC(6, h6) ACC(7, h7)
#undef ACC

        float af = unpack_sum(af2);
        float ai = unpack_sum(ai2);
        float ao = unpack_sum(ao2);
        float ac = unpack_sum(ac2);

#pragma unroll
        for (int off = 16; off > 0; off >>= 1) {
            af += __shfl_xor_sync(0xffffffffu, af, off);
            ai += __shfl_xor_sync(0xffffffffu, ai, off);
            ao += __shfl_xor_sync(0xffffffffu, ao, off);
            ac += __shfl_xor_sync(0xffffffffu, ac, off);
        }

        float fg = sigmoid_fast(af + xgf);
        float ig = sigmoid_fast(ai + xgi);
        float og = sigmoid_fast(ao + xgo);
        float gg = tanh_fast(ac + xgc);
        c = fmaf(fg, c, ig * gg);
        float hval = og * tanh_fast(c);

        if (lane == 0) {
            /* canon: -0 -> +0 (non-foldable), then sign flip => bits never zero */
            float canon = __fadd_rn(hval, 0.0f);
            float sval  = __uint_as_float(__float_as_uint(canon) ^ 0x80000000u);
            __stcg(&g_HV[(size_t)(t + 1) * NH + h_idx], sval);
        }
    }
}

/* =================== output GEMV =================== */
__global__ void __launch_bounds__(256) out_kernel(
    const float* __restrict__ Ahy, const float* __restrict__ by,
    float* __restrict__ out)
{
    const int w    = threadIdx.x >> 5;
    const int lane = threadIdx.x & 31;
    const int t    = blockIdx.x * 8 + w;
    if (t >= STEPS) return;

    const float* rowv = g_HV + (size_t)(t + 1) * NH + 4 * lane;
    const float* ap   = Ahy + 4 * lane;
    float a = 0.0f;
#pragma unroll
    for (int j = 0; j < 4; j++) {
        float4 v  = *(const float4*)(rowv + j * 128);   /* s = -h */
        float4 av = *(const float4*)(ap + j * 128);
        a = fmaf(av.x, -v.x, a);
        a = fmaf(av.y, -v.y, a);
        a = fmaf(av.z, -v.z, a);
        a = fmaf(av.w, -v.w, a);
    }
    a += __shfl_xor_sync(0xffffffffu, a, 16);
    a += __shfl_xor_sync(0xffffffffu, a, 8);
    a += __shfl_xor_sync(0xffffffffu, a, 4);
    a += __shfl_xor_sync(0xffffffffu, a, 2);
    a += __shfl_xor_sync(0xffffffffu, a, 1);
    if (lane == 0) out[t] = a + by[0];
}

/* =================== launch =================== */
extern "C" void kernel_launch(void* const* d_in, const int* in_sizes, int n_in,
                              void* d_out, int out_size)
{
    const float* x   = (const float*)d_in[0];
    const float* Wf  = (const float*)d_in[1];
    const float* Uf  = (const float*)d_in[2];
    const float* bf  = (const float*)d_in[3];
    const float* Wi  = (const float*)d_in[4];
    const float* Ui  = (const float*)d_in[5];
    const float* bi  = (const float*)d_in[6];
    const float* Wo  = (const float*)d_in[7];
    const float* Uo  = (const float*)d_in[8];
    const float* bo  = (const float*)d_in[9];
    const float* Wc  = (const float*)d_in[10];
    const float* Uc  = (const float*)d_in[11];
    const float* bc  = (const float*)d_in[12];
    const float* Ahy = (const float*)d_in[13];
    const float* by  = (const float*)d_in[14];
    float* out = (float*)d_out;

    init_kernel<<<1, 512>>>();

    dim3 ggrid((STEPS + GT_TT - 1) / GT_TT, NROWS / GT_ROWS);
    gates_kernel<<<ggrid, GT_TPB>>>(x, Wf, Wi, Wo, Wc, bf, bi, bo, bc);

    rec_kernel<<<NCTA, TPB>>>(Uf, Ui, Uo, Uc);

    out_kernel<<<(STEPS + 7) / 8, 256>>>(Ahy, by, out);
}